// round 11
// baseline (speedup 1.0000x reference)
#include <cuda_runtime.h>
#include <cuda_bf16.h>
#include <cstdint>

// BG_LSTM via warp-level HMMA: B=512, T=512, H=256, in=1.
// R8 topology (proven best): 16 clusters x 16 CTAs (non-portable), 128
// threads/CTA, 2 CTAs/SM. Cluster owns 32 batches; CTA rank owns 16 units
// (64 gate rows). W_hh SMEM-resident as bf16 hi/lo planes.
// R11 deltas vs R8: (1) h exchanged as separate hi/lo bf16 u32-pair planes
// -> staging is pure LDG.128->STS.128 (no PRMT repack); (2) MMA uses split
// accumulators (cA: main term, cB: two correction terms) -> 8 independent
// dependency chains per warp instead of 4x48-deep.
// Gates = Whi*hhi + Wlo*hhi + Whi*hlo, fp32 accum; one release/acquire
// cluster barrier per step.

#define TT 512
#define RANKS 16
#define NT 128
#define UPC 16
#define MROWS 64
#define ASTR 264

// h planes: [buf][tile][batch][unit-pair], u32 = (bf16 u+1 <<16)|(bf16 u)
__device__ uint32_t g_hi32[2][16][32][128];
__device__ uint32_t g_lo32[2][16][32][128];

extern __shared__ __align__(16) char smem_raw[];

// ---- SMEM offsets (from 1KB-aligned base) ----
#define OFF_ALO 33792u      // W hi plane: 64*264*2 = 33792
#define OFF_BHI 67584u
#define OFF_BLO 84480u
#define OFF_GS  101376u     // 4 warps x 2560
#define OFF_XS  111616u     // 16 steps x 32 b fp32 = 2048
#define SM_BYTES 114688

// ---------------- asm helpers ----------------
static __device__ __forceinline__ uint32_t smem_u32(const void* p) {
    uint32_t a;
    asm("{ .reg .u64 t; cvta.to.shared.u64 t, %1; cvt.u32.u64 %0, t; }"
        : "=r"(a) : "l"(p));
    return a;
}
static __device__ __forceinline__ void sts128(uint32_t a, uint4 v) {
    asm volatile("st.shared.v4.b32 [%0], {%1,%2,%3,%4};"
                 :: "r"(a), "r"(v.x), "r"(v.y), "r"(v.z), "r"(v.w));
}
static __device__ __forceinline__ void sts32f(uint32_t a, float v) {
    asm volatile("st.shared.f32 [%0], %1;" :: "r"(a), "f"(v));
}
static __device__ __forceinline__ void sts32u(uint32_t a, uint32_t v) {
    asm volatile("st.shared.b32 [%0], %1;" :: "r"(a), "r"(v));
}
static __device__ __forceinline__ float lds32f(uint32_t a) {
    float v; asm volatile("ld.shared.f32 %0, [%1];" : "=f"(v) : "r"(a));
    return v;
}
static __device__ __forceinline__ float4 lds128f(uint32_t a) {
    float4 v;
    asm volatile("ld.shared.v4.f32 {%0,%1,%2,%3}, [%4];"
                 : "=f"(v.x), "=f"(v.y), "=f"(v.z), "=f"(v.w) : "r"(a));
    return v;
}
static __device__ __forceinline__ void ldsm4(uint32_t* r, uint32_t a) {
    asm volatile("ldmatrix.sync.aligned.m8n8.x4.shared.b16 {%0,%1,%2,%3}, [%4];"
                 : "=r"(r[0]), "=r"(r[1]), "=r"(r[2]), "=r"(r[3]) : "r"(a));
}
static __device__ __forceinline__ void mma16816(float* c, const uint32_t* a,
                                                const uint32_t* b) {
    asm volatile(
        "mma.sync.aligned.m16n8k16.row.col.f32.bf16.bf16.f32 "
        "{%0,%1,%2,%3},{%4,%5,%6,%7},{%8,%9},{%0,%1,%2,%3};"
        : "+f"(c[0]), "+f"(c[1]), "+f"(c[2]), "+f"(c[3])
        : "r"(a[0]), "r"(a[1]), "r"(a[2]), "r"(a[3]), "r"(b[0]), "r"(b[1]));
}
static __device__ __forceinline__ void cluster_arrive_rel() {
    asm volatile("barrier.cluster.arrive.release.aligned;" ::: "memory");
}
static __device__ __forceinline__ void cluster_wait_acq() {
    asm volatile("barrier.cluster.wait.acquire.aligned;" ::: "memory");
}
static __device__ __forceinline__ float tanh_a(float x) {
    float y; asm("tanh.approx.f32 %0, %1;" : "=f"(y) : "f"(x)); return y;
}
static __device__ __forceinline__ float sigm(float x) {
    return fmaf(0.5f, tanh_a(0.5f * x), 0.5f);
}

__global__ void __launch_bounds__(NT, 1)
lstm_kernel(const float* __restrict__ x,    const float* __restrict__ wih,
            const float* __restrict__ whh,  const float* __restrict__ bih,
            const float* __restrict__ bhh,  const float* __restrict__ wfc,
            const float* __restrict__ bfc,  float* __restrict__ out)
{
    const int t      = threadIdx.x;
    const int lane   = t & 31;
    const int w      = t >> 5;          // warp 0..3
    const int cta    = blockIdx.x;
    const int rank   = cta % RANKS;
    const int cl     = cta / RANKS;     // tile 0..15
    const int batch0 = cl * 32;
    const int unit0  = rank * UPC;

    const uint32_t base = (smem_u32(smem_raw) + 1023u) & ~1023u;
    const uint32_t sAhi = base;
    const uint32_t sAlo = base + OFF_ALO;
    const uint32_t sBhi = base + OFF_BHI;
    const uint32_t sBlo = base + OFF_BLO;
    const uint32_t sGS  = base + OFF_GS;
    const uint32_t sXS  = base + OFF_XS;

    // ---- One-time: W' -> SMEM planes. Row m = u*4+g (u local). ----
    if (t < MROWS) {
        const int m = t;
        const float* wrow = whh + ((size_t)((m & 3) * 256 + unit0 + (m >> 2))) * 256;
        uint32_t ah = sAhi + (uint32_t)(m * ASTR * 2);
        uint32_t al = sAlo + (uint32_t)(m * ASTR * 2);
        #pragma unroll 8
        for (int k2 = 0; k2 < 128; k2++) {
            float2 wv = *(const float2*)(wrow + 2 * k2);
            __nv_bfloat16 hx = __float2bfloat16(wv.x);
            __nv_bfloat16 hy = __float2bfloat16(wv.y);
            float rx = wv.x - __bfloat162float(hx);
            float ry = wv.y - __bfloat162float(hy);
            uint32_t hi = ((uint32_t)__bfloat16_as_ushort(hy) << 16) |
                          (uint32_t)__bfloat16_as_ushort(hx);
            __nv_bfloat16 lx = __float2bfloat16(rx);
            __nv_bfloat16 ly = __float2bfloat16(ry);
            uint32_t lo = ((uint32_t)__bfloat16_as_ushort(ly) << 16) |
                          (uint32_t)__bfloat16_as_ushort(lx);
            sts32u(ah + 4u * k2, hi);
            sts32u(al + 4u * k2, lo);
        }
    }

    // ---- Per-thread activation params: u = t>>3 (0..15), b = 4(t&7)+j ----
    const int u  = t >> 3;
    const int bq = t & 7;
    float wihr[4], biasr[4];
    #pragma unroll
    for (int g = 0; g < 4; g++) {
        int r = g * 256 + unit0 + u;
        wihr[g]  = __ldg(&wih[r]);
        biasr[g] = __ldg(&bih[r]) + __ldg(&bhh[r]);
    }

    // ---- Zero h planes, buffer 0, my tile (1/16 per CTA) ----
    {
        uint32_t* zh = &g_hi32[0][cl][0][0];
        uint32_t* zl = &g_lo32[0][cl][0][0];
        __stcg(&zh[rank * 256 + t], 0u);
        __stcg(&zh[rank * 256 + t + NT], 0u);
        __stcg(&zl[rank * 256 + t], 0u);
        __stcg(&zl[rank * 256 + t + NT], 0u);
    }
    float cc[4] = {0.f, 0.f, 0.f, 0.f};

    // ---- ldmatrix lane base addresses (R8 layout) ----
    const uint32_t aOff =
        (uint32_t)(((16 * w + (lane & 15)) * ASTR + ((lane >> 4) * 8)) * 2);
    uint32_t bOff[2];
    #pragma unroll
    for (int P = 0; P < 2; P++) {
        int nB = 16 * P + (lane & 7) + (((lane >> 4) & 1) << 3);
        int ka = (lane & 8) ? 8 : 0;
        bOff[P] = (uint32_t)((nB * ASTR + ka) * 2);
    }

    __syncthreads();
    cluster_arrive_rel();
    cluster_wait_acq();

    int p = 0;
    for (int step = 0; step < TT; step++) {
        // ---- Stage B planes: pure LDG.128 -> STS.128 (8+8 per thread) ----
        {
            const uint4* srcH = (const uint4*)&g_hi32[p][cl][0][0];
            const uint4* srcL = (const uint4*)&g_lo32[p][cl][0][0];
            #pragma unroll
            for (int i = 0; i < 8; i++) {
                int id  = t + i * NT;        // 1024 granules of 16B / plane
                int b   = id >> 5;
                int col = id & 31;
                uint32_t o = (uint32_t)(b * (ASTR * 2) + col * 16);
                uint4 vh = __ldcg(&srcH[id]);
                uint4 vl = __ldcg(&srcL[id]);
                sts128(sBhi + o, vh);
                sts128(sBlo + o, vl);
            }
        }
        // ---- Stage x chunk every 16 steps: xs[(s&15)*32 + b] ----
        if ((step & 15) == 0) {
            int bx = t >> 2, i4 = t & 3;
            float4 v = __ldg((const float4*)&x[(size_t)(batch0 + bx) * TT + step] + i4);
            uint32_t a0 = sXS + (uint32_t)(((i4 * 4 + 0) * 32 + bx) * 4);
            sts32f(a0,        v.x);
            sts32f(a0 + 128u, v.y);
            sts32f(a0 + 256u, v.z);
            sts32f(a0 + 384u, v.w);
        }
        __syncthreads();

        // ---- MMA: 3-term split, SPLIT accumulators (8 chains/warp) ----
        float cA0[4] = {0,0,0,0}, cA1[4] = {0,0,0,0};
        float cA2[4] = {0,0,0,0}, cA3[4] = {0,0,0,0};
        float cB0[4] = {0,0,0,0}, cB1[4] = {0,0,0,0};
        float cB2[4] = {0,0,0,0}, cB3[4] = {0,0,0,0};
        uint32_t aHi = sAhi + aOff, aLo = sAlo + aOff;
        uint32_t bh0 = sBhi + bOff[0], bh1 = sBhi + bOff[1];
        uint32_t bl0 = sBlo + bOff[0], bl1 = sBlo + bOff[1];
        #pragma unroll 4
        for (int kt = 0; kt < 16; kt++) {
            uint32_t ah[4], al[4], bh[8], bl[8];
            ldsm4(ah, aHi);  ldsm4(al, aLo);
            ldsm4(bh, bh0);  ldsm4(bh + 4, bh1);
            ldsm4(bl, bl0);  ldsm4(bl + 4, bl1);
            aHi += 32; aLo += 32; bh0 += 32; bh1 += 32; bl0 += 32; bl1 += 32;
            mma16816(cA0, ah, bh);      mma16816(cA1, ah, bh + 2);
            mma16816(cA2, ah, bh + 4);  mma16816(cA3, ah, bh + 6);
            mma16816(cB0, al, bh);      mma16816(cB1, al, bh + 2);
            mma16816(cB2, al, bh + 4);  mma16816(cB3, al, bh + 6);
            mma16816(cB0, ah, bl);      mma16816(cB1, ah, bl + 2);
            mma16816(cB2, ah, bl + 4);  mma16816(cB3, ah, bl + 6);
        }
        #pragma unroll
        for (int i = 0; i < 4; i++) {
            cA0[i] += cB0[i];  cA1[i] += cB1[i];
            cA2[i] += cB2[i];  cA3[i] += cB3[i];
        }

        // ---- D fragments -> warp-private gates scratch ----
        {
            uint32_t gw = sGS + (uint32_t)(w * 2560);
            int mr = lane >> 2;            // m_local rows mr, mr+8
            int j0 = 2 * (lane & 3);
            float* cs[4] = {cA0, cA1, cA2, cA3};
            #pragma unroll
            for (int nt = 0; nt < 4; nt++) {
                int col = nt * 8 + j0;
                sts32f(gw + (uint32_t)((col    ) * 80 + mr * 4),       cs[nt][0]);
                sts32f(gw + (uint32_t)((col + 1) * 80 + mr * 4),       cs[nt][1]);
                sts32f(gw + (uint32_t)((col    ) * 80 + (mr + 8) * 4), cs[nt][2]);
                sts32f(gw + (uint32_t)((col + 1) * 80 + (mr + 8) * 4), cs[nt][3]);
            }
        }
        __syncwarp();

        // ---- Activations (warp-local): 4 cells (u, 4bq+j) ----
        float hv[4];
        {
            uint32_t gw = sGS + (uint32_t)(w * 2560) + (uint32_t)((lane >> 3) * 16);
            #pragma unroll
            for (int j = 0; j < 4; j++) {
                int b = 4 * bq + j;
                float4 gv = lds128f(gw + (uint32_t)(b * 80));
                float xv  = lds32f(sXS + (uint32_t)(((step & 15) * 32 + b) * 4));
                float gi = gv.x + fmaf(xv, wihr[0], biasr[0]);
                float gf = gv.y + fmaf(xv, wihr[1], biasr[1]);
                float gg = gv.z + fmaf(xv, wihr[2], biasr[2]);
                float go = gv.w + fmaf(xv, wihr[3], biasr[3]);
                float c = sigm(gf) * cc[j] + sigm(gi) * tanh_a(gg);
                cc[j] = c;
                hv[j] = sigm(go) * tanh_a(c);
            }
        }
        // ---- Pair units via shfl(8), store hi/lo plane u32s ----
        {
            float q[4];
            #pragma unroll
            for (int j = 0; j < 4; j++)
                q[j] = __shfl_down_sync(0xffffffffu, hv[j], 8);
            if (((lane >> 3) & 1) == 0) {      // u even: lanes 0-7, 16-23
                int up = (unit0 + u) >> 1;
                #pragma unroll
                for (int j = 0; j < 4; j++) {
                    int b = 4 * bq + j;
                    __nv_bfloat16 h0 = __float2bfloat16(hv[j]);
                    __nv_bfloat16 h1 = __float2bfloat16(q[j]);
                    uint32_t hi = ((uint32_t)__bfloat16_as_ushort(h1) << 16) |
                                  (uint32_t)__bfloat16_as_ushort(h0);
                    __nv_bfloat16 l0 = __float2bfloat16(hv[j] - __bfloat162float(h0));
                    __nv_bfloat16 l1 = __float2bfloat16(q[j]  - __bfloat162float(h1));
                    uint32_t lo = ((uint32_t)__bfloat16_as_ushort(l1) << 16) |
                                  (uint32_t)__bfloat16_as_ushort(l0);
                    __stcg(&g_hi32[p ^ 1][cl][b][up], hi);
                    __stcg(&g_lo32[p ^ 1][cl][b][up], lo);
                }
            }
        }

        cluster_arrive_rel();
        cluster_wait_acq();
        p ^= 1;
    }

    // ---- FC head (rank 0 CTA of each cluster); final h in buffer 0 ----
    if (rank == 0) {
        int b = t >> 2, seg = t & 3;   // 4 segments x 32 unit-pairs
        float s = 0.f;
        #pragma unroll 4
        for (int jj = 0; jj < 32; jj++) {
            int q = seg * 32 + jj;     // unit pair -> units 2q, 2q+1
            uint32_t hi = __ldcg(&g_hi32[0][cl][b][q]);
            uint32_t lo = __ldcg(&g_lo32[0][cl][b][q]);
            float h0 = __bfloat162float(__ushort_as_bfloat16((unsigned short)(hi & 0xFFFF))) +
                       __bfloat162float(__ushort_as_bfloat16((unsigned short)(lo & 0xFFFF)));
            float h1 = __bfloat162float(__ushort_as_bfloat16((unsigned short)(hi >> 16))) +
                       __bfloat162float(__ushort_as_bfloat16((unsigned short)(lo >> 16)));
            s = fmaf(fmaxf(h0, 0.f), __ldg(&wfc[2 * q]),     s);
            s = fmaf(fmaxf(h1, 0.f), __ldg(&wfc[2 * q + 1]), s);
        }
        sts32f(sGS + (uint32_t)((b * 4 + seg) * 4), s);
        __syncthreads();
        if (t < 32) {
            float tot = __ldg(bfc);
            #pragma unroll
            for (int sg = 0; sg < 4; sg++)
                tot += lds32f(sGS + (uint32_t)((t * 4 + sg) * 4));
            out[batch0 + t] = tot;
        }
    }
}

extern "C" void kernel_launch(void* const* d_in, const int* in_sizes, int n_in,
                              void* d_out, int out_size) {
    const float* x   = (const float*)d_in[0];
    const float* wih = (const float*)d_in[1];
    const float* whh = (const float*)d_in[2];
    const float* bih = (const float*)d_in[3];
    const float* bhh = (const float*)d_in[4];
    const float* wfc = (const float*)d_in[5];
    const float* bfc = (const float*)d_in[6];
    (void)in_sizes; (void)n_in; (void)out_size;

    cudaFuncSetAttribute(lstm_kernel,
                         cudaFuncAttributeMaxDynamicSharedMemorySize, SM_BYTES);
    cudaFuncSetAttribute(lstm_kernel,
                         cudaFuncAttributeNonPortableClusterSizeAllowed, 1);

    cudaLaunchConfig_t cfg = {};
    cfg.gridDim  = {256, 1, 1};
    cfg.blockDim = {NT, 1, 1};
    cfg.dynamicSmemBytes = SM_BYTES;
    cudaLaunchAttribute at[1];
    at[0].id = cudaLaunchAttributeClusterDimension;
    at[0].val.clusterDim = {RANKS, 1, 1};
    cfg.attrs = at; cfg.numAttrs = 1;
    cudaLaunchKernelEx(&cfg, lstm_kernel, x, wih, whh, bih, bhh, wfc, bfc,
                       (float*)d_out);
}